// round 1
// baseline (speedup 1.0000x reference)
#include <cuda_runtime.h>

#define C_DIM 64
#define ROWS_PER_BLOCK 256
#define MARGIN_F 0.01f
#define MAX_PARTIALS 4096

// 1/(C - i) table; overall 1/B factor applied once in the reduce kernel.
#define T1(i) (1.0f / (64.0f - (float)(i)))
#define T4(i) T1(i), T1((i)+1), T1((i)+2), T1((i)+3)
#define T16(i) T4(i), T4((i)+4), T4((i)+8), T4((i)+12)
__constant__ float c_invgap[C_DIM] = { T16(0), T16(16), T16(32), T16(48) };

__device__ float g_partials[MAX_PARTIALS];

__global__ void __launch_bounds__(ROWS_PER_BLOCK)
margin_loss_kernel(const float* __restrict__ cand,
                   const float* __restrict__ summ,
                   int B)
{
    const int row = blockIdx.x * ROWS_PER_BLOCK + threadIdx.x;

    float a[C_DIM];
    float total = 0.0f;

    if (row < B) {
        // Coalesced-enough vector loads: 16x LDG.128, front-batched by ptxas.
        const float4* rp = reinterpret_cast<const float4*>(cand + (size_t)row * C_DIM);
        #pragma unroll
        for (int i = 0; i < C_DIM / 4; i++) {
            float4 v = rp[i];
            a[4 * i + 0] = v.x;
            a[4 * i + 1] = v.y;
            a[4 * i + 2] = v.z;
            a[4 * i + 3] = v.w;
        }

        // Summary term: mean(relu(cand - summary)) -> weight 1/C here, 1/B later.
        const float s = summ[row];
        float s0 = 0.0f, s1 = 0.0f;
        #pragma unroll
        for (int x = 0; x < C_DIM; x += 2) {
            s0 += fmaxf(a[x]     - s, 0.0f);
            s1 += fmaxf(a[x + 1] - s, 0.0f);
        }
        total = (s0 + s1) * (1.0f / (float)C_DIM);

        // Fold margin into operands: a[x] += MARGIN * x, so every pair term is
        // relu(a[j+i] - a[j]).
        #pragma unroll
        for (int x = 0; x < C_DIM; x++)
            a[x] = __fmaf_rn(MARGIN_F, (float)x, a[x]);

        // All gaps i = 1..C-1. Two accumulators break the FADD chain.
        #pragma unroll
        for (int i = 1; i < C_DIM; i++) {
            float b0 = 0.0f, b1 = 0.0f;
            #pragma unroll
            for (int j = 0; j + i < C_DIM; j += 2) {
                // d = a[j+i] - a[j] coaxed to FFMA-imm (rt_SMSP=1)
                float d0 = __fmaf_rn(a[j], -1.0f, a[j + i]);
                float r0 = fmaxf(d0, 0.0f);
                b0 = __fmaf_rn(r0, 1.0f, b0);
                if (j + 1 + i < C_DIM) {
                    float d1 = __fmaf_rn(a[j + 1], -1.0f, a[j + 1 + i]);
                    float r1 = fmaxf(d1, 0.0f);
                    b1 = __fmaf_rn(r1, 1.0f, b1);
                }
            }
            total = __fmaf_rn(b0 + b1, c_invgap[i], total);
        }
    }

    // Deterministic block reduction.
    __shared__ float sred[ROWS_PER_BLOCK];
    sred[threadIdx.x] = total;
    __syncthreads();
    #pragma unroll
    for (int off = ROWS_PER_BLOCK / 2; off > 0; off >>= 1) {
        if (threadIdx.x < off)
            sred[threadIdx.x] += sred[threadIdx.x + off];
        __syncthreads();
    }
    if (threadIdx.x == 0)
        g_partials[blockIdx.x] = sred[0];
}

__global__ void __launch_bounds__(512)
reduce_kernel(float* __restrict__ out, int nblocks, float invB)
{
    __shared__ float sred[512];
    float v = 0.0f;
    for (int i = threadIdx.x; i < nblocks; i += 512)
        v += g_partials[i];
    sred[threadIdx.x] = v;
    __syncthreads();
    #pragma unroll
    for (int off = 256; off > 0; off >>= 1) {
        if (threadIdx.x < off)
            sred[threadIdx.x] += sred[threadIdx.x + off];
        __syncthreads();
    }
    if (threadIdx.x == 0)
        out[0] = sred[0] * invB;
}

extern "C" void kernel_launch(void* const* d_in, const int* in_sizes, int n_in,
                              void* d_out, int out_size)
{
    const float* cand = (const float*)d_in[0];   // [B, 64] f32
    const float* summ = (const float*)d_in[1];   // [B]     f32
    float* out = (float*)d_out;

    const int B = in_sizes[1];
    const int nblocks = (B + ROWS_PER_BLOCK - 1) / ROWS_PER_BLOCK;
    const float invB = 1.0f / (float)B;

    margin_loss_kernel<<<nblocks, ROWS_PER_BLOCK>>>(cand, summ, B);
    reduce_kernel<<<1, 512>>>(out, nblocks, invB);
}